// round 8
// baseline (speedup 1.0000x reference)
#include <cuda_runtime.h>
#include <cstdint>

#define S_LEN 2048
#define BATCH 128
#define IN_DIM 64
#define HID 128
#define G4 512
#define OUT_DIM 64
#define NGROUP 32
#define CPG 4
#define BG 4
#define NCTA (NGROUP * CPG)

// ---- static device scratch ----
__device__ float g_Xp[(size_t)S_LEN * BATCH * G4];   // [s][b][n]
__device__ float g_hs[(size_t)S_LEN * BATCH * HID];  // [s][b][h]

// ---- rec dynamic smem layout (float offsets) ----
#define WO_F      0                    // 64 rows x 129 ull = 16512 floats
#define SH_H_F    16512                // [r][2 x 68]
#define SH_XH_F   (SH_H_F + 544)       // [r][4 x 68]
#define SG_F      (SH_XH_F + 1088)     // [r][128]
#define MB_F      (SG_F + 512)         // 2 x u64
#define PT_F      (MB_F + 4)           // 16 x u32
#define REC_SMEM  ((PT_F + 16 + 4) * 4)
#define OUT_SMEM  ((128 * 136 + 128 * 65) * 4)

__device__ __forceinline__ float sigf(float v) {
    return __fdividef(1.f, 1.f + __expf(-v));
}
__device__ __forceinline__ float tanhf_fast(float x) {
    float cx = fminf(fmaxf(x, -15.f), 15.f);
    float e = __expf(2.f * cx);
    return __fdividef(e - 1.f, e + 1.f);
}

__device__ __forceinline__ uint32_t smem_u32(const void* p) {
    uint32_t a;
    asm("{ .reg .u64 t; cvta.to.shared.u64 t, %1; cvt.u32.u64 %0, t; }" : "=r"(a) : "l"(p));
    return a;
}
__device__ __forceinline__ uint32_t mapa_u32(uint32_t local_addr, int rank) {
    uint32_t r;
    asm("mapa.shared::cluster.u32 %0, %1, %2;" : "=r"(r) : "r"(local_addr), "r"(rank));
    return r;
}
#define CLUSTER_SYNC_() do { \
    asm volatile("barrier.cluster.arrive.aligned;" ::: "memory"); \
    asm volatile("barrier.cluster.wait.aligned;" ::: "memory"); \
} while (0)

#define MBAR_INIT(addr, cnt) \
    asm volatile("mbarrier.init.shared.b64 [%0], %1;" :: "r"(addr), "r"(cnt) : "memory")
#define MBAR_ARM(addr, bytes) \
    asm volatile("mbarrier.arrive.expect_tx.shared.b64 _, [%0], %1;" :: "r"(addr), "r"(bytes) : "memory")
#define MBAR_WAIT(addr, parity) do { \
    asm volatile("{\n\t.reg .pred P1;\n\t" \
        "WAIT_%=:\n\t" \
        "mbarrier.try_wait.parity.acquire.cta.shared::cta.b64 P1, [%0], %1, 0x989680;\n\t" \
        "@P1 bra.uni DONE_%=;\n\t" \
        "bra.uni WAIT_%=;\n\t" \
        "DONE_%=:\n\t}" \
        :: "r"(addr), "r"(parity) : "memory"); \
} while (0)

__device__ __forceinline__ void st_async_f32(uint32_t daddr, uint32_t dmbar, float v) {
    asm volatile("st.async.shared::cluster.mbarrier::complete_tx::bytes.f32 [%0], %1, [%2];"
                 :: "r"(daddr), "f"(v), "r"(dmbar) : "memory");
}
__device__ __forceinline__ void st_async_v2f32(uint32_t daddr, uint32_t dmbar, float a, float b) {
    asm volatile("st.async.shared::cluster.mbarrier::complete_tx::bytes.v2.f32 [%0], {%1, %2}, [%3];"
                 :: "r"(daddr), "f"(a), "f"(b), "r"(dmbar) : "memory");
}

__device__ __forceinline__ void ffma2(unsigned long long& d, unsigned long long a, unsigned long long b) {
    asm("fma.rn.f32x2 %0, %1, %2, %0;" : "+l"(d) : "l"(a), "l"(b));
}
__device__ __forceinline__ unsigned long long pack2(float a, float b) {
    unsigned long long p;
    asm("mov.b64 %0, {%1, %2};" : "=l"(p) : "f"(a), "f"(b));
    return p;
}
__device__ __forceinline__ float sum2(unsigned long long p) {
    float lo, hi;
    asm("mov.b64 {%0, %1}, %2;" : "=f"(lo), "=f"(hi) : "l"(p));
    return lo + hi;
}

// ---- Kernel 1: Xp[s][b][n] = b_out[n] + sum_i x[b][i][s] * Wx_out[i][n] ----
__global__ __launch_bounds__(256) void xproj_kernel(const float* __restrict__ x,
                                                    const float* __restrict__ Wx,
                                                    const float* __restrict__ bo) {
    __shared__ float xs[IN_DIM * 33];
    const int s = blockIdx.x;
    const int b0 = blockIdx.y * 32;
    const int t = threadIdx.x;
    const int b = t & 31;
    const int n0 = (t >> 5) * 64;

    for (int q = t; q < 32 * IN_DIM; q += 256) {
        int bb = q >> 6, i = q & 63;
        xs[i * 33 + bb] = x[((size_t)(b0 + bb) * IN_DIM + i) * S_LEN + s];
    }
    __syncthreads();

    float acc[64];
#pragma unroll
    for (int j = 0; j < 64; j++) acc[j] = 0.f;
#pragma unroll 2
    for (int k = 0; k < IN_DIM; k++) {
        float xv = xs[k * 33 + b];
        const float4* wr = (const float4*)(Wx + (size_t)k * G4 + n0);
#pragma unroll
        for (int j4 = 0; j4 < 16; j4++) {
            float4 w = __ldg(&wr[j4]);
            acc[4 * j4 + 0] = fmaf(xv, w.x, acc[4 * j4 + 0]);
            acc[4 * j4 + 1] = fmaf(xv, w.y, acc[4 * j4 + 1]);
            acc[4 * j4 + 2] = fmaf(xv, w.z, acc[4 * j4 + 2]);
            acc[4 * j4 + 3] = fmaf(xv, w.w, acc[4 * j4 + 3]);
        }
    }
#pragma unroll
    for (int j = 0; j < 64; j++) {
        g_Xp[((size_t)s * BATCH + b0 + b) * G4 + n0 + j] = acc[j] + __ldg(&bo[n0 + j]);
    }
}

// outer GEMM block: 16 k (8 weight pairs), weights from smem (stride-129 rows)
#define OUTER_BLK(I0, BASE) do { \
    const ulonglong2* hp = (const ulonglong2*)(sh_h + (BASE)); \
    _Pragma("unroll") \
    for (int q = 0; q < 4; q++) { \
        ulonglong2 x0 = hp[q], x1 = hp[q + 34], x2 = hp[q + 68], x3 = hp[q + 102]; \
        unsigned long long wA = wo_row[((I0) + 2 * q) * 129]; \
        unsigned long long wB = wo_row[((I0) + 2 * q + 1) * 129]; \
        ffma2(a0, x0.x, wA); ffma2(a0, x0.y, wB); \
        ffma2(a1, x1.x, wA); ffma2(a1, x1.y, wB); \
        ffma2(a2, x2.x, wA); ffma2(a2, x2.y, wB); \
        ffma2(a3, x3.x, wA); ffma2(a3, x3.y, wB); \
    } \
} while (0)

// inner GEMM block: 32 k' (16 register weight pairs)
#define INNER_BLK(WI0, BASE) do { \
    const ulonglong2* hp = (const ulonglong2*)(sh_xh + (BASE)); \
    _Pragma("unroll") \
    for (int q = 0; q < 8; q++) { \
        ulonglong2 x0 = hp[q], x1 = hp[q + 68], x2 = hp[q + 136], x3 = hp[q + 204]; \
        unsigned long long wA = wi[(WI0) + 2 * q], wB = wi[(WI0) + 2 * q + 1]; \
        ffma2(a0, x0.x, wA); ffma2(a0, x0.y, wB); \
        ffma2(a1, x1.x, wA); ffma2(a1, x1.y, wB); \
        ffma2(a2, x2.x, wA); ffma2(a2, x2.y, wB); \
        ffma2(a3, x3.x, wA); ffma2(a3, x3.y, wB); \
    } \
} while (0)

// ---- Kernel 2: persistent recurrence; cluster of 4 CTAs = 1 group (4 batch rows).
//      Inner weights in regs, outer in smem; own-block-first K order overlaps
//      DSMEM exchange latency with compute. ----
__global__ __launch_bounds__(256, 1) __cluster_dims__(CPG, 1, 1)
void rec_kernel(const float* __restrict__ Wh_out,
                const float* __restrict__ Wx_in,
                const float* __restrict__ Wh_in,
                const float* __restrict__ b_in) {
    extern __shared__ float sm[];
    unsigned long long* wo_sm = (unsigned long long*)sm;        // [row<64][129]
    float* sh_h  = sm + SH_H_F;
    float* sh_xh = sm + SH_XH_F;
    float* sg    = sm + SG_F;
    unsigned long long* mbars = (unsigned long long*)(sm + MB_F);
    uint32_t* ptab = (uint32_t*)(sm + PT_F);                    // per rank: xh, h, bx, bh

    const int cta = blockIdx.x;
    const int g   = cta >> 2;
    const int t   = threadIdx.x;
    const int j   = t >> 1;            // gate column 0..127
    const int kp  = t & 1;             // K-half
    uint32_t cs;
    asm("mov.u32 %0, %%cluster_ctarank;" : "=r"(cs));
    const int gcol = (j >> 5) * 128 + (int)cs * 32 + (j & 31);

    // ---- per-thread K block list: own block first, then 3 remote ----
    int b0, b1, b2, b3;
    {
        int rem[6]; int c = 0;
#pragma unroll
        for (int b = 0; b < 8; b++) if ((b >> 1) != (int)cs) rem[c++] = b;
        b0 = 2 * (int)cs + kp;
        b1 = rem[kp * 3 + 0]; b2 = rem[kp * 3 + 1]; b3 = rem[kp * 3 + 2];
    }
    // outer (16-k blocks) and inner (32-k' blocks) share the same block ids
    const int ob0 = (b0 >> 2) * 68 + (b0 & 3) * 16;
    const int ob1 = (b1 >> 2) * 68 + (b1 & 3) * 16;
    const int ob2 = (b2 >> 2) * 68 + (b2 & 3) * 16;
    const int ob3 = (b3 >> 2) * 68 + (b3 & 3) * 16;
    const int ib0 = (b0 >> 1) * 68 + (b0 & 1) * 32;
    const int ib1 = (b1 >> 1) * 68 + (b1 & 1) * 32;
    const int ib2 = (b2 >> 1) * 68 + (b2 & 1) * 32;
    const int ib3 = (b3 >> 1) * 68 + (b3 & 1) * 32;

    // ---- outer weights into smem (block-permuted per thread) ----
    unsigned long long* wo_row = wo_sm + (size_t)(kp * 32) * 129 + j;
#pragma unroll
    for (int i = 0; i < 32; i++) {
        int b = (i < 8) ? b0 : ((i < 16) ? b1 : ((i < 24) ? b2 : b3));
        int p = b * 8 + (i & 7);
        wo_row[i * 129] = pack2(Wh_out[(size_t)(2 * p) * G4 + gcol],
                                Wh_out[(size_t)(2 * p + 1) * G4 + gcol]);
    }
    // ---- inner weights in regs (block-permuted): wi[i] = {Wx_in[h], Wh_in[h]} ----
    unsigned long long wi[64];
#pragma unroll
    for (int i = 0; i < 64; i++) {
        int b = (i < 16) ? b0 : ((i < 32) ? b1 : ((i < 48) ? b2 : b3));
        int h = b * 16 + (i & 15);
        wi[i] = pack2(Wx_in[(size_t)h * G4 + gcol], Wh_in[(size_t)h * G4 + gcol]);
    }
    const float bin = b_in[gcol];

    // peer table + mbarriers
    if (t < CPG) {
        ptab[t * 4 + 0] = mapa_u32(smem_u32(sh_xh), t);
        ptab[t * 4 + 1] = mapa_u32(smem_u32(sh_h), t);
        ptab[t * 4 + 2] = mapa_u32(smem_u32(&mbars[0]), t);
        ptab[t * 4 + 3] = mapa_u32(smem_u32(&mbars[1]), t);
    }
    const uint32_t bx_loc = smem_u32(&mbars[0]);
    const uint32_t bh_loc = smem_u32(&mbars[1]);
    if (t == 0) {
        MBAR_INIT(bx_loc, 1);
        MBAR_INIT(bh_loc, 1);
        MBAR_ARM(bx_loc, 3072u);   // phase 0: 3 peers x 128 x 8B
        MBAR_ARM(bh_loc, 1536u);   // phase 0: 3 peers x 128 x 4B
    }
    for (int q = t; q < BG * 2 * 68; q += 256) sh_h[q] = 0.f;  // h0 = 0
    __syncthreads();
    CLUSTER_SYNC_();

    // owner role (t < 128)
    const int bl = t >> 5, hc = t & 31;
    const int h_own = (int)cs * 32 + hc;
    const int kxi = 2 * h_own;
    const int loc_x = bl * 272 + (kxi >> 6) * 68 + (kxi & 63);
    const int loc_h = bl * 136 + (h_own >> 6) * 68 + (h_own & 63);
    const uint32_t offb_x = (uint32_t)loc_x * 4u;
    const uint32_t offb_h = (uint32_t)loc_h * 4u;
    float c_reg = 0.f, cn_reg = 0.f, o_reg = 0.f;

    const float* xp_base = g_Xp + (size_t)(g * BG) * G4 + gcol + (size_t)(kp * 2) * G4;

    for (int s = 0; s < S_LEN; s++) {
        const float* xp = xp_base + (size_t)s * BATCH * G4;
        float xpa = __ldcs(xp), xpb = __ldcs(xp + G4);

        // ---- outer GEMM: own block first (local h, synced), then wait peers ----
        unsigned long long a0 = 0ull, a1 = 0ull, a2 = 0ull, a3 = 0ull;
        OUTER_BLK(0, ob0);
        if (s > 0) {
            MBAR_WAIT(bh_loc, (uint32_t)((s - 1) & 1));
            if (t == 0) MBAR_ARM(bh_loc, 1536u);
        }
        OUTER_BLK(8, ob1);
        OUTER_BLK(16, ob2);
        OUTER_BLK(24, ob3);
        {
            float s0 = sum2(a0), s1 = sum2(a1), s2 = sum2(a2), s3 = sum2(a3);
            s0 += __shfl_xor_sync(0xffffffffu, s0, 1);
            s1 += __shfl_xor_sync(0xffffffffu, s1, 1);
            s2 += __shfl_xor_sync(0xffffffffu, s2, 1);
            s3 += __shfl_xor_sync(0xffffffffu, s3, 1);
            if (kp == 0) { sg[0 * 128 + j] = s0 + xpa; sg[1 * 128 + j] = s1 + xpb; }
            else         { sg[2 * 128 + j] = s2 + xpa; sg[3 * 128 + j] = s3 + xpb; }
        }
        __syncthreads();

        // ---- elementwise 1: own (x_in,h_in) local, 3 peers via st.async ----
        if (t < 128) {
            float i_ = sigf(sg[bl * 128 + hc]);
            float f_ = sigf(sg[bl * 128 + 32 + hc]);
            o_reg    = sigf(sg[bl * 128 + 64 + hc]);
            float g_ = tanhf_fast(sg[bl * 128 + 96 + hc]);
            float xin = i_ * g_;
            float hin = f_ * c_reg;
            *(float2*)(sh_xh + loc_x) = make_float2(xin, hin);
#pragma unroll
            for (int r = 0; r < CPG; r++)
                if (r != (int)cs)
                    st_async_v2f32(ptab[r * 4 + 0] + offb_x, ptab[r * 4 + 2], xin, hin);
        }
        __syncthreads();   // own xh visible

        // ---- inner GEMM: own block first, then wait peers ----
        a0 = a1 = a2 = a3 = 0ull;
        INNER_BLK(0, ib0);
        MBAR_WAIT(bx_loc, (uint32_t)(s & 1));
        if (t == 0) MBAR_ARM(bx_loc, 3072u);
        INNER_BLK(16, ib1);
        INNER_BLK(32, ib2);
        INNER_BLK(48, ib3);
        {
            float s0 = sum2(a0), s1 = sum2(a1), s2 = sum2(a2), s3 = sum2(a3);
            s0 += __shfl_xor_sync(0xffffffffu, s0, 1);
            s1 += __shfl_xor_sync(0xffffffffu, s1, 1);
            s2 += __shfl_xor_sync(0xffffffffu, s2, 1);
            s3 += __shfl_xor_sync(0xffffffffu, s3, 1);
            if (kp == 0) { sg[0 * 128 + j] = s0 + bin; sg[1 * 128 + j] = s1 + bin; }
            else         { sg[2 * 128 + j] = s2 + bin; sg[3 * 128 + j] = s3 + bin; }
        }
        __syncthreads();

        // ---- elementwise 2: update state; own h local, 3 peers via st.async ----
        if (t < 128) {
            float ii = sigf(sg[bl * 128 + hc]);
            float fi = sigf(sg[bl * 128 + 32 + hc]);
            float oi = sigf(sg[bl * 128 + 64 + hc]);
            float gg = tanhf_fast(sg[bl * 128 + 96 + hc]);
            cn_reg = fi * cn_reg + ii * gg;
            c_reg  = oi * tanhf_fast(cn_reg);
            float hnew = o_reg * tanhf_fast(c_reg);
            sh_h[loc_h] = hnew;
#pragma unroll
            for (int r = 0; r < CPG; r++)
                if (r != (int)cs)
                    st_async_f32(ptab[r * 4 + 1] + offb_h, ptab[r * 4 + 3], hnew);
            g_hs[((size_t)s * BATCH + g * BG + bl) * HID + h_own] = hnew;
        }
        __syncthreads();   // own h visible for next step's early outer
    }
    MBAR_WAIT(bh_loc, 1u);   // drain final h exchange ((S_LEN-1)&1 == 1)
    CLUSTER_SYNC_();
}

// ---- Kernel 3: out[b][s][o] = b_lin[o] + sum_h hs[s][b][h] * W_lin[o][h] ----
__global__ __launch_bounds__(256) void out_kernel(const float* __restrict__ Wl,
                                                  const float* __restrict__ bl,
                                                  float* __restrict__ out) {
    extern __shared__ float sm[];
    float* hsb = sm;               // transposed [h][b], pad 136
    float* wls = sm + 128 * 136;   // [h][o] pad 65

    const int s = blockIdx.x;
    const int t = threadIdx.x;
    const int o = t & 63;
    const int b0 = (t >> 6) * 32;

    const float* src = g_hs + (size_t)s * BATCH * HID;   // [b][h]
    for (int q = t; q < 16384; q += 256) {
        int b = q >> 7, h = q & 127;
        hsb[h * 136 + b] = src[q];
    }
    for (int q = t; q < 8192; q += 256) {
        int oo = q >> 7, k = q & 127;
        wls[k * 65 + oo] = Wl[q];
    }
    __syncthreads();

    float acc[32];
#pragma unroll
    for (int jj = 0; jj < 32; jj++) acc[jj] = 0.f;
#pragma unroll 2
    for (int k = 0; k < HID; k++) {
        float wv = wls[k * 65 + o];
        const float4* hr = (const float4*)(hsb + k * 136 + b0);
#pragma unroll
        for (int j4 = 0; j4 < 8; j4++) {
            float4 hv = hr[j4];
            acc[4 * j4 + 0] = fmaf(hv.x, wv, acc[4 * j4 + 0]);
            acc[4 * j4 + 1] = fmaf(hv.y, wv, acc[4 * j4 + 1]);
            acc[4 * j4 + 2] = fmaf(hv.z, wv, acc[4 * j4 + 2]);
            acc[4 * j4 + 3] = fmaf(hv.w, wv, acc[4 * j4 + 3]);
        }
    }
    float bb = bl[o];
#pragma unroll
    for (int jj = 0; jj < 32; jj++) {
        out[((size_t)(b0 + jj) * S_LEN + s) * OUT_DIM + o] = acc[jj] + bb;
    }
}

extern "C" void kernel_launch(void* const* d_in, const int* in_sizes, int n_in,
                              void* d_out, int out_size) {
    const float* x      = (const float*)d_in[0];
    const float* Wx_out = (const float*)d_in[1];
    const float* Wh_out = (const float*)d_in[2];
    const float* b_out  = (const float*)d_in[3];
    const float* Wx_in  = (const float*)d_in[4];
    const float* Wh_in  = (const float*)d_in[5];
    const float* b_in   = (const float*)d_in[6];
    const float* W_lin  = (const float*)d_in[7];
    const float* b_lin  = (const float*)d_in[8];
    float* out = (float*)d_out;

    cudaFuncSetAttribute(rec_kernel, cudaFuncAttributeMaxDynamicSharedMemorySize, REC_SMEM);
    cudaFuncSetAttribute(out_kernel, cudaFuncAttributeMaxDynamicSharedMemorySize, OUT_SMEM);

    xproj_kernel<<<dim3(S_LEN, BATCH / 32), 256>>>(x, Wx_out, b_out);
    rec_kernel<<<NCTA, 256, REC_SMEM>>>(Wh_out, Wx_in, Wh_in, b_in);
    out_kernel<<<S_LEN, 256, OUT_SMEM>>>(W_lin, b_lin, out);
}

// round 9
// speedup vs baseline: 1.0707x; 1.0707x over previous
#include <cuda_runtime.h>
#include <cstdint>

#define S_LEN 2048
#define BATCH 128
#define IN_DIM 64
#define HID 128
#define G4 512
#define OUT_DIM 64
#define NGROUP 32
#define CPG 4
#define BG 4
#define NCTA (NGROUP * CPG)

// ---- static device scratch ----
__device__ float g_Xp[(size_t)S_LEN * BATCH * G4];   // [s][b][n]
__device__ float g_hs[(size_t)S_LEN * BATCH * HID];  // [s][b][h]

#define OUT_SMEM ((128 * 136 + 128 * 65) * 4)

__device__ __forceinline__ float sigf(float v) {
    return __fdividef(1.f, 1.f + __expf(-v));
}
__device__ __forceinline__ float tanhf_fast(float x) {
    float cx = fminf(fmaxf(x, -15.f), 15.f);
    float e = __expf(2.f * cx);
    return __fdividef(e - 1.f, e + 1.f);
}

__device__ __forceinline__ uint32_t smem_u32(const void* p) {
    uint32_t a;
    asm("{ .reg .u64 t; cvta.to.shared.u64 t, %1; cvt.u32.u64 %0, t; }" : "=r"(a) : "l"(p));
    return a;
}
__device__ __forceinline__ uint32_t mapa_u32(uint32_t local_addr, int rank) {
    uint32_t r;
    asm("mapa.shared::cluster.u32 %0, %1, %2;" : "=r"(r) : "r"(local_addr), "r"(rank));
    return r;
}
#define CLUSTER_SYNC_() do { \
    asm volatile("barrier.cluster.arrive.aligned;" ::: "memory"); \
    asm volatile("barrier.cluster.wait.aligned;" ::: "memory"); \
} while (0)

#define MBAR_INIT(addr, cnt) \
    asm volatile("mbarrier.init.shared.b64 [%0], %1;" :: "r"(addr), "r"(cnt) : "memory")
#define MBAR_ARM(addr, bytes) \
    asm volatile("mbarrier.arrive.expect_tx.shared.b64 _, [%0], %1;" :: "r"(addr), "r"(bytes) : "memory")
#define MBAR_WAIT(addr, parity) do { \
    asm volatile("{\n\t.reg .pred P1;\n\t" \
        "WAIT_%=:\n\t" \
        "mbarrier.try_wait.parity.acquire.cta.shared::cta.b64 P1, [%0], %1, 0x989680;\n\t" \
        "@P1 bra.uni DONE_%=;\n\t" \
        "bra.uni WAIT_%=;\n\t" \
        "DONE_%=:\n\t}" \
        :: "r"(addr), "r"(parity) : "memory"); \
} while (0)

__device__ __forceinline__ void st_async_f32(uint32_t daddr, uint32_t dmbar, float v) {
    asm volatile("st.async.shared::cluster.mbarrier::complete_tx::bytes.f32 [%0], %1, [%2];"
                 :: "r"(daddr), "f"(v), "r"(dmbar) : "memory");
}
__device__ __forceinline__ void st_async_v2f32(uint32_t daddr, uint32_t dmbar, float a, float b) {
    asm volatile("st.async.shared::cluster.mbarrier::complete_tx::bytes.v2.f32 [%0], {%1, %2}, [%3];"
                 :: "r"(daddr), "f"(a), "f"(b), "r"(dmbar) : "memory");
}

__device__ __forceinline__ void ffma2(unsigned long long& d, unsigned long long a, unsigned long long b) {
    asm("fma.rn.f32x2 %0, %1, %2, %0;" : "+l"(d) : "l"(a), "l"(b));
}
__device__ __forceinline__ unsigned long long pack2(float a, float b) {
    unsigned long long p;
    asm("mov.b64 %0, {%1, %2};" : "=l"(p) : "f"(a), "f"(b));
    return p;
}
__device__ __forceinline__ float sum2(unsigned long long p) {
    float lo, hi;
    asm("mov.b64 {%0, %1}, %2;" : "=f"(lo), "=f"(hi) : "l"(p));
    return lo + hi;
}

// ---- Kernel 1: Xp[s][b][n] = b_out[n] + sum_i x[b][i][s] * Wx_out[i][n] ----
__global__ __launch_bounds__(256) void xproj_kernel(const float* __restrict__ x,
                                                    const float* __restrict__ Wx,
                                                    const float* __restrict__ bo) {
    __shared__ float xs[IN_DIM * 33];
    const int s = blockIdx.x;
    const int b0 = blockIdx.y * 32;
    const int t = threadIdx.x;
    const int b = t & 31;
    const int n0 = (t >> 5) * 64;

    for (int q = t; q < 32 * IN_DIM; q += 256) {
        int bb = q >> 6, i = q & 63;
        xs[i * 33 + bb] = x[((size_t)(b0 + bb) * IN_DIM + i) * S_LEN + s];
    }
    __syncthreads();

    float acc[64];
#pragma unroll
    for (int j = 0; j < 64; j++) acc[j] = 0.f;
#pragma unroll 2
    for (int k = 0; k < IN_DIM; k++) {
        float xv = xs[k * 33 + b];
        const float4* wr = (const float4*)(Wx + (size_t)k * G4 + n0);
#pragma unroll
        for (int j4 = 0; j4 < 16; j4++) {
            float4 w = __ldg(&wr[j4]);
            acc[4 * j4 + 0] = fmaf(xv, w.x, acc[4 * j4 + 0]);
            acc[4 * j4 + 1] = fmaf(xv, w.y, acc[4 * j4 + 1]);
            acc[4 * j4 + 2] = fmaf(xv, w.z, acc[4 * j4 + 2]);
            acc[4 * j4 + 3] = fmaf(xv, w.w, acc[4 * j4 + 3]);
        }
    }
#pragma unroll
    for (int j = 0; j < 64; j++) {
        g_Xp[((size_t)s * BATCH + b0 + b) * G4 + n0 + j] = acc[j] + __ldg(&bo[n0 + j]);
    }
}

// outer GEMM block: 16 k, 8 register weight pairs
#define OUTER_BLK(I0, BASE) do { \
    const ulonglong2* hp = (const ulonglong2*)(sh_h + (BASE)); \
    _Pragma("unroll") \
    for (int q = 0; q < 4; q++) { \
        ulonglong2 x0 = hp[q], x1 = hp[q + 34], x2 = hp[q + 68], x3 = hp[q + 102]; \
        unsigned long long wA = wo[(I0) + 2 * q], wB = wo[(I0) + 2 * q + 1]; \
        ffma2(a0, x0.x, wA); ffma2(a0, x0.y, wB); \
        ffma2(a1, x1.x, wA); ffma2(a1, x1.y, wB); \
        ffma2(a2, x2.x, wA); ffma2(a2, x2.y, wB); \
        ffma2(a3, x3.x, wA); ffma2(a3, x3.y, wB); \
    } \
} while (0)

// inner GEMM block: 32 k' (16 register weight pairs)
#define INNER_BLK(WI0, BASE) do { \
    const ulonglong2* hp = (const ulonglong2*)(sh_xh + (BASE)); \
    _Pragma("unroll") \
    for (int q = 0; q < 8; q++) { \
        ulonglong2 x0 = hp[q], x1 = hp[q + 68], x2 = hp[q + 136], x3 = hp[q + 204]; \
        unsigned long long wA = wi[(WI0) + 2 * q], wB = wi[(WI0) + 2 * q + 1]; \
        ffma2(a0, x0.x, wA); ffma2(a0, x0.y, wB); \
        ffma2(a1, x1.x, wA); ffma2(a1, x1.y, wB); \
        ffma2(a2, x2.x, wA); ffma2(a2, x2.y, wB); \
        ffma2(a3, x3.x, wA); ffma2(a3, x3.y, wB); \
    } \
} while (0)

// ---- Kernel 2: persistent recurrence; cluster of 4 CTAs = 1 group (4 batch rows).
//      All weights register-resident (block-permuted: own block first);
//      mbarrier waits deferred behind own-block compute. ----
__global__ __launch_bounds__(256, 1) __cluster_dims__(CPG, 1, 1)
void rec_kernel(const float* __restrict__ Wh_out,
                const float* __restrict__ Wx_in,
                const float* __restrict__ Wh_in,
                const float* __restrict__ b_in) {
    __shared__ __align__(16) float sh_h[BG * 2 * 68];     // staged h  [r][2 x 68]
    __shared__ __align__(16) float sh_xh[BG * 4 * 68];    // staged xh [r][4 x 68] (k'=2h interleave)
    __shared__ float sg[BG * 128];                        // gates [r][j]
    __shared__ __align__(8) unsigned long long mbars[2];  // [0]=xh, [1]=h
    __shared__ uint32_t ptab[CPG * 4];                    // per rank: xh, h, bx, bh

    const int cta = blockIdx.x;
    const int g   = cta >> 2;
    const int t   = threadIdx.x;
    const int j   = t >> 1;            // gate column 0..127
    const int kp  = t & 1;
    uint32_t cs;
    asm("mov.u32 %0, %%cluster_ctarank;" : "=r"(cs));
    const int gcol = (j >> 5) * 128 + (int)cs * 32 + (j & 31);

    // ---- per-thread K block list: own block first, then 3 remote ----
    int b0, b1, b2, b3;
    {
        int rem[6]; int c = 0;
#pragma unroll
        for (int b = 0; b < 8; b++) if ((b >> 1) != (int)cs) rem[c++] = b;
        b0 = 2 * (int)cs + kp;
        b1 = rem[kp * 3 + 0]; b2 = rem[kp * 3 + 1]; b3 = rem[kp * 3 + 2];
    }
    const int ob0 = (b0 >> 2) * 68 + (b0 & 3) * 16;   // outer: 8 blocks of 16 k
    const int ob1 = (b1 >> 2) * 68 + (b1 & 3) * 16;
    const int ob2 = (b2 >> 2) * 68 + (b2 & 3) * 16;
    const int ob3 = (b3 >> 2) * 68 + (b3 & 3) * 16;
    const int ib0 = (b0 >> 1) * 68 + (b0 & 1) * 32;   // inner: 8 blocks of 32 k'
    const int ib1 = (b1 >> 1) * 68 + (b1 & 1) * 32;
    const int ib2 = (b2 >> 1) * 68 + (b2 & 1) * 32;
    const int ib3 = (b3 >> 1) * 68 + (b3 & 1) * 32;

    // ---- register-resident weights, block-permuted ----
    unsigned long long wo[32];   // outer: 8 pairs per block
#pragma unroll
    for (int i = 0; i < 32; i++) {
        int b = (i < 8) ? b0 : ((i < 16) ? b1 : ((i < 24) ? b2 : b3));
        int p = b * 8 + (i & 7);
        wo[i] = pack2(Wh_out[(size_t)(2 * p) * G4 + gcol],
                      Wh_out[(size_t)(2 * p + 1) * G4 + gcol]);
    }
    unsigned long long wi[64];   // inner: 16 pairs per block, {Wx_in[h], Wh_in[h]}
#pragma unroll
    for (int i = 0; i < 64; i++) {
        int b = (i < 16) ? b0 : ((i < 32) ? b1 : ((i < 48) ? b2 : b3));
        int h = b * 16 + (i & 15);
        wi[i] = pack2(Wx_in[(size_t)h * G4 + gcol], Wh_in[(size_t)h * G4 + gcol]);
    }
    const float bin = b_in[gcol];

    // peer table + mbarriers
    if (t < CPG) {
        ptab[t * 4 + 0] = mapa_u32(smem_u32(sh_xh), t);
        ptab[t * 4 + 1] = mapa_u32(smem_u32(sh_h), t);
        ptab[t * 4 + 2] = mapa_u32(smem_u32(&mbars[0]), t);
        ptab[t * 4 + 3] = mapa_u32(smem_u32(&mbars[1]), t);
    }
    const uint32_t bx_loc = smem_u32(&mbars[0]);
    const uint32_t bh_loc = smem_u32(&mbars[1]);
    if (t == 0) {
        MBAR_INIT(bx_loc, 1);
        MBAR_INIT(bh_loc, 1);
        MBAR_ARM(bx_loc, 3072u);   // 3 peers x 128 x 8B
        MBAR_ARM(bh_loc, 1536u);   // 3 peers x 128 x 4B
    }
    for (int q = t; q < BG * 2 * 68; q += 256) sh_h[q] = 0.f;  // h0 = 0
    __syncthreads();
    CLUSTER_SYNC_();

    // owner role (t < 128)
    const int bl = t >> 5, hc = t & 31;
    const int h_own = (int)cs * 32 + hc;
    const int kxi = 2 * h_own;
    const int loc_x = bl * 272 + (kxi >> 6) * 68 + (kxi & 63);
    const int loc_h = bl * 136 + (h_own >> 6) * 68 + (h_own & 63);
    const uint32_t offb_x = (uint32_t)loc_x * 4u;
    const uint32_t offb_h = (uint32_t)loc_h * 4u;
    float c_reg = 0.f, cn_reg = 0.f, o_reg = 0.f;

    const float* xp_base = g_Xp + (size_t)(g * BG) * G4 + gcol + (size_t)(kp * 2) * G4;

    for (int s = 0; s < S_LEN; s++) {
        const float* xp = xp_base + (size_t)s * BATCH * G4;
        float xpa = __ldcs(xp), xpb = __ldcs(xp + G4);

        // ---- outer GEMM: own block first (local h), wait peers behind it ----
        unsigned long long a0 = 0ull, a1 = 0ull, a2 = 0ull, a3 = 0ull;
        OUTER_BLK(0, ob0);
        if (s > 0) {
            MBAR_WAIT(bh_loc, (uint32_t)((s - 1) & 1));
            if (t == 0) MBAR_ARM(bh_loc, 1536u);
        }
        OUTER_BLK(8, ob1);
        OUTER_BLK(16, ob2);
        OUTER_BLK(24, ob3);
        {
            float s0 = sum2(a0), s1 = sum2(a1), s2 = sum2(a2), s3 = sum2(a3);
            s0 += __shfl_xor_sync(0xffffffffu, s0, 1);
            s1 += __shfl_xor_sync(0xffffffffu, s1, 1);
            s2 += __shfl_xor_sync(0xffffffffu, s2, 1);
            s3 += __shfl_xor_sync(0xffffffffu, s3, 1);
            if (kp == 0) { sg[0 * 128 + j] = s0 + xpa; sg[1 * 128 + j] = s1 + xpb; }
            else         { sg[2 * 128 + j] = s2 + xpa; sg[3 * 128 + j] = s3 + xpb; }
        }
        __syncthreads();

        // ---- elementwise 1: own (x_in,h_in) local, 3 peers via st.async ----
        if (t < 128) {
            float i_ = sigf(sg[bl * 128 + hc]);
            float f_ = sigf(sg[bl * 128 + 32 + hc]);
            o_reg    = sigf(sg[bl * 128 + 64 + hc]);
            float g_ = tanhf_fast(sg[bl * 128 + 96 + hc]);
            float xin = i_ * g_;
            float hin = f_ * c_reg;
            *(float2*)(sh_xh + loc_x) = make_float2(xin, hin);
#pragma unroll
            for (int r = 0; r < CPG; r++)
                if (r != (int)cs)
                    st_async_v2f32(ptab[r * 4 + 0] + offb_x, ptab[r * 4 + 2], xin, hin);
        }
        __syncthreads();   // own xh visible

        // ---- inner GEMM: own block first, wait peers behind it ----
        a0 = a1 = a2 = a3 = 0ull;
        INNER_BLK(0, ib0);
        MBAR_WAIT(bx_loc, (uint32_t)(s & 1));
        if (t == 0) MBAR_ARM(bx_loc, 3072u);
        INNER_BLK(16, ib1);
        INNER_BLK(32, ib2);
        INNER_BLK(48, ib3);
        {
            float s0 = sum2(a0), s1 = sum2(a1), s2 = sum2(a2), s3 = sum2(a3);
            s0 += __shfl_xor_sync(0xffffffffu, s0, 1);
            s1 += __shfl_xor_sync(0xffffffffu, s1, 1);
            s2 += __shfl_xor_sync(0xffffffffu, s2, 1);
            s3 += __shfl_xor_sync(0xffffffffu, s3, 1);
            if (kp == 0) { sg[0 * 128 + j] = s0 + bin; sg[1 * 128 + j] = s1 + bin; }
            else         { sg[2 * 128 + j] = s2 + bin; sg[3 * 128 + j] = s3 + bin; }
        }
        __syncthreads();

        // ---- elementwise 2: update state; own h local, 3 peers via st.async ----
        if (t < 128) {
            float ii = sigf(sg[bl * 128 + hc]);
            float fi = sigf(sg[bl * 128 + 32 + hc]);
            float oi = sigf(sg[bl * 128 + 64 + hc]);
            float gg = tanhf_fast(sg[bl * 128 + 96 + hc]);
            cn_reg = fi * cn_reg + ii * gg;
            c_reg  = oi * tanhf_fast(cn_reg);
            float hnew = o_reg * tanhf_fast(c_reg);
            sh_h[loc_h] = hnew;
#pragma unroll
            for (int r = 0; r < CPG; r++)
                if (r != (int)cs)
                    st_async_f32(ptab[r * 4 + 1] + offb_h, ptab[r * 4 + 3], hnew);
            g_hs[((size_t)s * BATCH + g * BG + bl) * HID + h_own] = hnew;
        }
        __syncthreads();   // own h visible for next step's early outer block
    }
    MBAR_WAIT(bh_loc, 1u);   // drain final h exchange ((S_LEN-1)&1 == 1)
    CLUSTER_SYNC_();
}

// ---- Kernel 3: out[b][s][o] = b_lin[o] + sum_h hs[s][b][h] * W_lin[o][h] ----
__global__ __launch_bounds__(256) void out_kernel(const float* __restrict__ Wl,
                                                  const float* __restrict__ bl,
                                                  float* __restrict__ out) {
    extern __shared__ float sm[];
    float* hsb = sm;               // transposed [h][b], pad 136
    float* wls = sm + 128 * 136;   // [h][o] pad 65

    const int s = blockIdx.x;
    const int t = threadIdx.x;
    const int o = t & 63;
    const int b0 = (t >> 6) * 32;

    const float* src = g_hs + (size_t)s * BATCH * HID;   // [b][h]
    for (int q = t; q < 16384; q += 256) {
        int b = q >> 7, h = q & 127;
        hsb[h * 136 + b] = src[q];
    }
    for (int q = t; q < 8192; q += 256) {
        int oo = q >> 7, k = q & 127;
        wls[k * 65 + oo] = Wl[q];
    }
    __syncthreads();

    float acc[32];
#pragma unroll
    for (int jj = 0; jj < 32; jj++) acc[jj] = 0.f;
#pragma unroll 2
    for (int k = 0; k < HID; k++) {
        float wv = wls[k * 65 + o];
        const float4* hr = (const float4*)(hsb + k * 136 + b0);
#pragma unroll
        for (int j4 = 0; j4 < 8; j4++) {
            float4 hv = hr[j4];
            acc[4 * j4 + 0] = fmaf(hv.x, wv, acc[4 * j4 + 0]);
            acc[4 * j4 + 1] = fmaf(hv.y, wv, acc[4 * j4 + 1]);
            acc[4 * j4 + 2] = fmaf(hv.z, wv, acc[4 * j4 + 2]);
            acc[4 * j4 + 3] = fmaf(hv.w, wv, acc[4 * j4 + 3]);
        }
    }
    float bb = bl[o];
#pragma unroll
    for (int jj = 0; jj < 32; jj++) {
        out[((size_t)(b0 + jj) * S_LEN + s) * OUT_DIM + o] = acc[jj] + bb;
    }
}

extern "C" void kernel_launch(void* const* d_in, const int* in_sizes, int n_in,
                              void* d_out, int out_size) {
    const float* x      = (const float*)d_in[0];
    const float* Wx_out = (const float*)d_in[1];
    const float* Wh_out = (const float*)d_in[2];
    const float* b_out  = (const float*)d_in[3];
    const float* Wx_in  = (const float*)d_in[4];
    const float* Wh_in  = (const float*)d_in[5];
    const float* b_in   = (const float*)d_in[6];
    const float* W_lin  = (const float*)d_in[7];
    const float* b_lin  = (const float*)d_in[8];
    float* out = (float*)d_out;

    cudaFuncSetAttribute(out_kernel, cudaFuncAttributeMaxDynamicSharedMemorySize, OUT_SMEM);

    xproj_kernel<<<dim3(S_LEN, BATCH / 32), 256>>>(x, Wx_out, b_out);
    rec_kernel<<<NCTA, 256>>>(Wh_out, Wx_in, Wh_in, b_in);
    out_kernel<<<S_LEN, 256, OUT_SMEM>>>(W_lin, b_lin, out);
}